// round 2
// baseline (speedup 1.0000x reference)
#include <cuda_runtime.h>
#include <stdint.h>

#define DIM 1280
#define NC  8192
#define MAX_ROWS 16384

#define BM 128
#define BN 128
#define BK 16

// scratch (no dynamic allocation allowed)
__device__ float g_xf[(size_t)MAX_ROWS * DIM];          // normalized x
__device__ float g_d2[NC];                              // codebook column norms^2
__device__ unsigned long long g_best[MAX_ROWS];         // packed (dist_key<<32 | code)

// ---------------------------------------------------------------------------
// order-preserving float -> uint32 key (min float == min uint)
__device__ __forceinline__ unsigned int fkey(float f) {
    unsigned int u = __float_as_uint(f);
    return (u & 0x80000000u) ? ~u : (u | 0x80000000u);
}

// ---------------------------------------------------------------------------
// warp-per-row: norm + exact-division normalize (matches reference's xf/norm)
__global__ void normalize_kernel(const float* __restrict__ x, int n_rows) {
    int gwarp = (blockIdx.x * blockDim.x + threadIdx.x) >> 5;
    int lane  = threadIdx.x & 31;
    if (gwarp >= n_rows) return;
    const float* xr = x + (size_t)gwarp * DIM;
    float s = 0.f;
    #pragma unroll 4
    for (int k = lane; k < DIM; k += 32) { float v = xr[k]; s = fmaf(v, v, s); }
    #pragma unroll
    for (int o = 16; o; o >>= 1) s += __shfl_xor_sync(0xFFFFFFFFu, s, o);
    float norm = fmaxf(sqrtf(s), 1e-12f);
    float* xo = g_xf + (size_t)gwarp * DIM;
    #pragma unroll 4
    for (int k = lane; k < DIM; k += 32) xo[k] = xr[k] / norm;
}

// column norms^2 of codebook (coalesced: adjacent threads adjacent cols)
__global__ void d2_kernel(const float* __restrict__ cb) {
    int c = blockIdx.x * blockDim.x + threadIdx.x;
    if (c >= NC) return;
    float s = 0.f;
    #pragma unroll 4
    for (int k = 0; k < DIM; k++) { float v = cb[(size_t)k * NC + c]; s = fmaf(v, v, s); }
    g_d2[c] = s;
}

__global__ void init_best_kernel(int n_rows) {
    int i = blockIdx.x * blockDim.x + threadIdx.x;
    if (i < n_rows) g_best[i] = ~0ull;
}

// ---------------------------------------------------------------------------
// 128x128x16 fp32 GEMM tile + fused argmin epilogue
__global__ __launch_bounds__(256, 2)
void gemm_argmin_kernel(const float* __restrict__ cb, int n_rows) {
    __shared__ float As[BK][132];                  // padded, stored transposed
    __shared__ float Bs[BK][BN];
    __shared__ unsigned long long best_s[BM];

    const int tid = threadIdx.x;
    const int rowBase = blockIdx.y * BM;
    const int colBase = blockIdx.x * BN;

    const int tx = tid & 15;        // col group
    const int ty = tid >> 4;        // row group

    float acc[8][8];
    #pragma unroll
    for (int i = 0; i < 8; i++)
        #pragma unroll
        for (int j = 0; j < 8; j++) acc[i][j] = 0.f;

    // global load indexing (2 float4 of A, 2 float4 of B per thread per tile)
    const int aRow0 = tid >> 2;            // 0..63
    const int aKK4  = tid & 3;             // float4 index in k (0..3)
    const float* gA0 = g_xf + (size_t)(rowBase + aRow0) * DIM + aKK4 * 4;
    const float* gA1 = gA0 + (size_t)64 * DIM;

    const int bKK0 = tid >> 5;             // 0..7
    const int bC4  = tid & 31;             // float4 index in cols (0..31)
    const float* gB0 = cb + (size_t)bKK0 * NC + colBase + bC4 * 4;
    const float* gB1 = gB0 + (size_t)8 * NC;

    float4 ra0, ra1, rb0, rb1;

    // prefetch tile 0
    ra0 = *(const float4*)(gA0);
    ra1 = *(const float4*)(gA1);
    rb0 = *(const float4*)(gB0);
    rb1 = *(const float4*)(gB1);

    // store tile 0
    {
        As[aKK4 * 4 + 0][aRow0]      = ra0.x;
        As[aKK4 * 4 + 1][aRow0]      = ra0.y;
        As[aKK4 * 4 + 2][aRow0]      = ra0.z;
        As[aKK4 * 4 + 3][aRow0]      = ra0.w;
        As[aKK4 * 4 + 0][aRow0 + 64] = ra1.x;
        As[aKK4 * 4 + 1][aRow0 + 64] = ra1.y;
        As[aKK4 * 4 + 2][aRow0 + 64] = ra1.z;
        As[aKK4 * 4 + 3][aRow0 + 64] = ra1.w;
        *(float4*)&Bs[bKK0][bC4 * 4]     = rb0;
        *(float4*)&Bs[bKK0 + 8][bC4 * 4] = rb1;
    }
    __syncthreads();

    const int NT = DIM / BK;   // 80
    for (int t = 1; t <= NT; t++) {
        if (t < NT) {
            size_t ka = (size_t)t * BK;
            ra0 = *(const float4*)(gA0 + ka);
            ra1 = *(const float4*)(gA1 + ka);
            size_t kb = (size_t)t * BK * NC;
            rb0 = *(const float4*)(gB0 + kb);
            rb1 = *(const float4*)(gB1 + kb);
        }

        #pragma unroll
        for (int kk = 0; kk < BK; kk++) {
            float4 a0 = *(const float4*)&As[kk][ty * 8];
            float4 a1 = *(const float4*)&As[kk][ty * 8 + 4];
            float4 b0 = *(const float4*)&Bs[kk][tx * 8];
            float4 b1 = *(const float4*)&Bs[kk][tx * 8 + 4];
            float av[8] = {a0.x, a0.y, a0.z, a0.w, a1.x, a1.y, a1.z, a1.w};
            float bv[8] = {b0.x, b0.y, b0.z, b0.w, b1.x, b1.y, b1.z, b1.w};
            #pragma unroll
            for (int i = 0; i < 8; i++)
                #pragma unroll
                for (int j = 0; j < 8; j++)
                    acc[i][j] = fmaf(av[i], bv[j], acc[i][j]);
        }
        __syncthreads();

        if (t < NT) {
            As[aKK4 * 4 + 0][aRow0]      = ra0.x;
            As[aKK4 * 4 + 1][aRow0]      = ra0.y;
            As[aKK4 * 4 + 2][aRow0]      = ra0.z;
            As[aKK4 * 4 + 3][aRow0]      = ra0.w;
            As[aKK4 * 4 + 0][aRow0 + 64] = ra1.x;
            As[aKK4 * 4 + 1][aRow0 + 64] = ra1.y;
            As[aKK4 * 4 + 2][aRow0 + 64] = ra1.z;
            As[aKK4 * 4 + 3][aRow0 + 64] = ra1.w;
            *(float4*)&Bs[bKK0][bC4 * 4]     = rb0;
            *(float4*)&Bs[bKK0 + 8][bC4 * 4] = rb1;
            __syncthreads();
        }
    }

    // ---- argmin epilogue ----
    if (tid < BM) best_s[tid] = ~0ull;
    __syncthreads();

    unsigned long long lb[8];
    #pragma unroll
    for (int i = 0; i < 8; i++) lb[i] = ~0ull;

    #pragma unroll
    for (int j = 0; j < 8; j++) {
        int col = colBase + tx * 8 + j;
        float d2v = g_d2[col];
        #pragma unroll
        for (int i = 0; i < 8; i++) {
            float dist = d2v - 2.0f * acc[i][j];
            unsigned long long pk =
                ((unsigned long long)fkey(dist) << 32) | (unsigned int)col;
            lb[i] = (pk < lb[i]) ? pk : lb[i];
        }
    }
    #pragma unroll
    for (int i = 0; i < 8; i++)
        atomicMin(&best_s[ty * 8 + i], lb[i]);
    __syncthreads();

    if (tid < BM)
        atomicMin(&g_best[rowBase + tid], best_s[tid]);
}

// ---------------------------------------------------------------------------
__global__ void write_inds_kernel(float* __restrict__ out, int n_rows) {
    int r = blockIdx.x * blockDim.x + threadIdx.x;
    if (r < n_rows)
        out[r] = (float)(unsigned int)(g_best[r] & 0xFFFFFFFFull);
}

// quantized[d, r] = cb[d, ind[r]]   flattened C-order, written at out+offset
__global__ void gather_kernel(const float* __restrict__ cb,
                              float* __restrict__ out,
                              int n_rows, long long offset) {
    int r = blockIdx.x * blockDim.x + threadIdx.x;
    int d = blockIdx.y;
    if (r >= n_rows) return;
    unsigned int ind = (unsigned int)(g_best[r] & 0xFFFFFFFFull);
    out[offset + (size_t)d * n_rows + r] = cb[(size_t)d * NC + ind];
}

// ---------------------------------------------------------------------------
extern "C" void kernel_launch(void* const* d_in, const int* in_sizes, int n_in,
                              void* d_out, int out_size) {
    const float* x  = (const float*)d_in[0];
    const float* cb = (const float*)d_in[1];
    float* out = (float*)d_out;

    int n_rows = in_sizes[0] / DIM;
    if (n_rows > MAX_ROWS) n_rows = MAX_ROWS;

    // phase 0: scratch prep (must rerun every launch for graph-replay determinism)
    normalize_kernel<<<(n_rows * 32 + 255) / 256, 256>>>(x, n_rows);
    d2_kernel<<<(NC + 255) / 256, 256>>>(cb);
    init_best_kernel<<<(n_rows + 255) / 256, 256>>>(n_rows);

    // phase 1: GEMM + fused argmin
    dim3 grid(NC / BN, (n_rows + BM - 1) / BM);
    gemm_argmin_kernel<<<grid, 256>>>(cb, n_rows);

    // phase 2: outputs. Expected layout: [inds (n_rows)] ++ [quantized (DIM*n_rows)]
    long long full = (long long)n_rows + (long long)n_rows * DIM;
    if ((long long)out_size >= full) {
        write_inds_kernel<<<(n_rows + 255) / 256, 256>>>(out, n_rows);
        dim3 g2((n_rows + 255) / 256, DIM);
        gather_kernel<<<g2, 256>>>(cb, out, n_rows, (long long)n_rows);
    } else if ((long long)out_size == (long long)n_rows * DIM) {
        dim3 g2((n_rows + 255) / 256, DIM);
        gather_kernel<<<g2, 256>>>(cb, out, n_rows, 0);
    } else {
        write_inds_kernel<<<(n_rows + 255) / 256, 256>>>(out, n_rows);
    }
}

// round 6
// speedup vs baseline: 4.3369x; 4.3369x over previous
#include <cuda_runtime.h>
#include <cuda_bf16.h>
#include <stdint.h>

#define DIM 1280
#define NC  8192
#define MAX_ROWS 16384

#define BM 128
#define BN 128
#define BK 64                      // bf16 elements per k-chunk (128 bytes/row)
#define NCH (DIM / BK)             // 20
#define TILES_N (NC / BN)          // 64
#define GROUP_M 16

// stage layout (bytes): Ah, Al, Bh, Bl each 128*64*2 = 16384
#define ST_A_HI 0
#define ST_A_LO 16384
#define ST_B_HI 32768
#define ST_B_LO 49152
#define STAGE_BYTES 65536
#define SMEM_DYN (2 * STAGE_BYTES)   // 131072

// ---- device scratch ----
__device__ __nv_bfloat16 g_a_hi[(size_t)MAX_ROWS * DIM];
__device__ __nv_bfloat16 g_a_lo[(size_t)MAX_ROWS * DIM];
__device__ __nv_bfloat16 g_b_hi[(size_t)NC * DIM];       // transposed [N][K]
__device__ __nv_bfloat16 g_b_lo[(size_t)NC * DIM];
__device__ float g_d2[NC];
__device__ unsigned long long g_best[MAX_ROWS];

// ---------------------------------------------------------------------------
__device__ __forceinline__ uint32_t smem_u32(const void* p) {
    uint32_t a;
    asm("{ .reg .u64 t; cvta.to.shared.u64 t, %1; cvt.u32.u64 %0, t; }"
        : "=r"(a) : "l"(p));
    return a;
}
__device__ __forceinline__ unsigned int fkey(float f) {
    unsigned int u = __float_as_uint(f);
    return (u & 0x80000000u) ? ~u : (u | 0x80000000u);
}
#define SWZ(o) ((o) ^ ((((uint32_t)(o)) >> 3) & 0x70))

__device__ __forceinline__ void cp16(uint32_t dst, const void* src) {
    asm volatile("cp.async.cg.shared.global [%0], [%1], 16;" :: "r"(dst), "l"(src));
}
#define CP_COMMIT() asm volatile("cp.async.commit_group;" ::: "memory")

__device__ __forceinline__ void ldsm4(uint32_t& r0, uint32_t& r1, uint32_t& r2,
                                      uint32_t& r3, uint32_t addr) {
    asm volatile("ldmatrix.sync.aligned.m8n8.x4.shared.b16 {%0,%1,%2,%3}, [%4];"
                 : "=r"(r0), "=r"(r1), "=r"(r2), "=r"(r3) : "r"(addr));
}
__device__ __forceinline__ void mma_bf16(float* c, uint32_t a0, uint32_t a1,
                                         uint32_t a2, uint32_t a3,
                                         uint32_t b0, uint32_t b1) {
    asm volatile(
        "mma.sync.aligned.m16n8k16.row.col.f32.bf16.bf16.f32 "
        "{%0,%1,%2,%3}, {%4,%5,%6,%7}, {%8,%9}, {%0,%1,%2,%3};"
        : "+f"(c[0]), "+f"(c[1]), "+f"(c[2]), "+f"(c[3])
        : "r"(a0), "r"(a1), "r"(a2), "r"(a3), "r"(b0), "r"(b1));
}

// ---------------------------------------------------------------------------
// prep: normalize rows of x, bf16 hi/lo split
__global__ void normalize_split_kernel(const float* __restrict__ x, int n_rows) {
    int gwarp = (blockIdx.x * blockDim.x + threadIdx.x) >> 5;
    int lane  = threadIdx.x & 31;
    if (gwarp >= n_rows) return;
    const float* xr = x + (size_t)gwarp * DIM;
    float s = 0.f;
    #pragma unroll 4
    for (int k = lane; k < DIM; k += 32) { float v = xr[k]; s = fmaf(v, v, s); }
    #pragma unroll
    for (int o = 16; o; o >>= 1) s += __shfl_xor_sync(0xFFFFFFFFu, s, o);
    float norm = fmaxf(sqrtf(s), 1e-12f);
    __nv_bfloat16* oh = g_a_hi + (size_t)gwarp * DIM;
    __nv_bfloat16* ol = g_a_lo + (size_t)gwarp * DIM;
    #pragma unroll 4
    for (int k = lane; k < DIM; k += 32) {
        float v = xr[k] / norm;
        __nv_bfloat16 hi = __float2bfloat16(v);
        __nv_bfloat16 lo = __float2bfloat16(v - __bfloat162float(hi));
        oh[k] = hi; ol[k] = lo;
    }
}

// prep: transpose codebook [K,N] -> [N,K] with bf16 hi/lo split
__global__ void transpose_split_kernel(const float* __restrict__ cb) {
    __shared__ float t[32][33];
    int n0 = blockIdx.x * 32;
    int k0 = blockIdx.y * 32;
    int tx = threadIdx.x, ty = threadIdx.y;  // 32 x 8
    #pragma unroll
    for (int j = 0; j < 4; j++)
        t[ty + 8 * j][tx] = cb[(size_t)(k0 + ty + 8 * j) * NC + n0 + tx];
    __syncthreads();
    #pragma unroll
    for (int j = 0; j < 4; j++) {
        int n = n0 + ty + 8 * j;
        int k = k0 + tx;
        float v = t[tx][ty + 8 * j];
        __nv_bfloat16 hi = __float2bfloat16(v);
        __nv_bfloat16 lo = __float2bfloat16(v - __bfloat162float(hi));
        g_b_hi[(size_t)n * DIM + k] = hi;
        g_b_lo[(size_t)n * DIM + k] = lo;
    }
}

__global__ void d2_kernel(const float* __restrict__ cb) {
    int c = blockIdx.x * blockDim.x + threadIdx.x;
    if (c >= NC) return;
    float s = 0.f;
    #pragma unroll 4
    for (int k = 0; k < DIM; k++) { float v = cb[(size_t)k * NC + c]; s = fmaf(v, v, s); }
    g_d2[c] = s;
}

__global__ void init_best_kernel(int n_rows) {
    int i = blockIdx.x * blockDim.x + threadIdx.x;
    if (i < n_rows) g_best[i] = ~0ull;
}

// ---------------------------------------------------------------------------
// 3xBF16 split mma.sync GEMM (128x128x64 chunks) + fused argmin epilogue
__global__ __launch_bounds__(256, 1)
void gemm_mma_kernel(int mtiles) {
    extern __shared__ char smem[];
    __shared__ float d2s[BN];
    __shared__ unsigned long long best_s[BM];

    const uint32_t sb = smem_u32(smem);
    const int tid  = threadIdx.x;
    const int wid  = tid >> 5;
    const int lane = tid & 31;

    // supertile mapping
    int bid = blockIdx.x;
    int per_group = GROUP_M * TILES_N;
    int g  = bid / per_group;
    int r  = bid % per_group;
    int gm = mtiles - g * GROUP_M; if (gm > GROUP_M) gm = GROUP_M;
    int mt = g * GROUP_M + (r % gm);
    int nt = r / gm;
    const int rowBase = mt * BM;
    const int colBase = nt * BN;

    if (tid < BN) d2s[tid] = g_d2[colBase + tid];
    if (tid < BM) best_s[tid] = ~0ull;

    const __nv_bfloat16* Ah = g_a_hi + (size_t)rowBase * DIM;
    const __nv_bfloat16* Al = g_a_lo + (size_t)rowBase * DIM;
    const __nv_bfloat16* Bh = g_b_hi + (size_t)colBase * DIM;
    const __nv_bfloat16* Bl = g_b_lo + (size_t)colBase * DIM;

    auto load_chunk = [&](int c, int st) {
        uint32_t base = sb + st * STAGE_BYTES;
        int kb = c * BK;
        #pragma unroll
        for (int j = 0; j < 4; j++) {
            int i = tid + j * 256;             // 0..1023
            int row = i >> 3, c16 = i & 7;
            uint32_t off = SWZ(row * 128 + c16 * 16);
            const __nv_bfloat16* pa = Ah + (size_t)row * DIM + kb + c16 * 8;
            const __nv_bfloat16* pl = Al + (size_t)row * DIM + kb + c16 * 8;
            const __nv_bfloat16* pbh = Bh + (size_t)row * DIM + kb + c16 * 8;
            const __nv_bfloat16* pbl = Bl + (size_t)row * DIM + kb + c16 * 8;
            cp16(base + ST_A_HI + off, pa);
            cp16(base + ST_A_LO + off, pl);
            cp16(base + ST_B_HI + off, pbh);
            cp16(base + ST_B_LO + off, pbl);
        }
        CP_COMMIT();
    };

    // warp tiling: 2 (M) x 4 (N); warp tile 64 x 32
    const int wm = (wid >> 2) * 64;
    const int wn = (wid & 3) * 32;

    float acc[4][4][4];
    #pragma unroll
    for (int i = 0; i < 4; i++)
        #pragma unroll
        for (int j = 0; j < 4; j++)
            #pragma unroll
            for (int k = 0; k < 4; k++) acc[i][j][k] = 0.f;

    // precomputed ldmatrix address components
    const int lm  = lane >> 3;     // matrix index 0..3
    const int lr  = lane & 7;      // row within matrix
    // A: matrices (m0: r+0,k+0) (m1: r+8,k+0) (m2: r+0,k+16B) (m3: r+8,k+16B)
    const int a_row  = wm + ((lm & 1) << 3) + lr;
    const int a_koff = (lm >> 1) << 4;
    // B: matrices (m0: n+0,k+0) (m1: n+0,k+16B) (m2: n+8,k+0) (m3: n+8,k+16B)
    const int b_row  = wn + ((lm >> 1) << 3) + lr;
    const int b_koff = (lm & 1) << 4;

    load_chunk(0, 0);

    for (int c = 0; c < NCH; c++) {
        int st = c & 1;
        if (c + 1 < NCH) {
            load_chunk(c + 1, st ^ 1);
            asm volatile("cp.async.wait_group 1;" ::: "memory");
        } else {
            asm volatile("cp.async.wait_group 0;" ::: "memory");
        }
        __syncthreads();

        uint32_t base = sb + st * STAGE_BYTES;
        #pragma unroll
        for (int ks = 0; ks < 4; ks++) {
            uint32_t ah[4][4], al[4][4], bh[4][2], bl[4][2];
            #pragma unroll
            for (int ma = 0; ma < 4; ma++) {
                uint32_t ra = SWZ((a_row + ma * 16) * 128 + ks * 32 + a_koff);
                ldsm4(ah[ma][0], ah[ma][1], ah[ma][2], ah[ma][3], base + ST_A_HI + ra);
                ldsm4(al[ma][0], al[ma][1], al[ma][2], al[ma][3], base + ST_A_LO + ra);
            }
            #pragma unroll
            for (int nb = 0; nb < 2; nb++) {
                uint32_t rb = SWZ((b_row + nb * 16) * 128 + ks * 32 + b_koff);
                ldsm4(bh[2 * nb][0], bh[2 * nb][1], bh[2 * nb + 1][0], bh[2 * nb + 1][1],
                      base + ST_B_HI + rb);
                ldsm4(bl[2 * nb][0], bl[2 * nb][1], bl[2 * nb + 1][0], bl[2 * nb + 1][1],
                      base + ST_B_LO + rb);
            }
            #pragma unroll
            for (int ma = 0; ma < 4; ma++)
                #pragma unroll
                for (int na = 0; na < 4; na++) {
                    mma_bf16(acc[ma][na], ah[ma][0], ah[ma][1], ah[ma][2], ah[ma][3],
                             bh[na][0], bh[na][1]);
                    mma_bf16(acc[ma][na], ah[ma][0], ah[ma][1], ah[ma][2], ah[ma][3],
                             bl[na][0], bl[na][1]);
                    mma_bf16(acc[ma][na], al[ma][0], al[ma][1], al[ma][2], al[ma][3],
                             bh[na][0], bh[na][1]);
                }
        }
        __syncthreads();
    }

    // ---- argmin epilogue ----
    // acc[ma][na][c]: rows wm+ma*16+(lane>>2)+8*(c>>1); cols wn+na*8+2*(lane&3)+(c&1)
    const int erow = lane >> 2;
    const int ecol = 2 * (lane & 3);
    #pragma unroll
    for (int ma = 0; ma < 4; ma++) {
        #pragma unroll
        for (int h = 0; h < 2; h++) {
            unsigned long long best = ~0ull;
            #pragma unroll
            for (int na = 0; na < 4; na++) {
                #pragma unroll
                for (int j = 0; j < 2; j++) {
                    int cl = wn + na * 8 + ecol + j;
                    float dist = d2s[cl] - 2.0f * acc[ma][na][2 * h + j];
                    unsigned long long pk =
                        ((unsigned long long)fkey(dist) << 32) |
                        (unsigned int)(colBase + cl);
                    best = (pk < best) ? pk : best;
                }
            }
            #pragma unroll
            for (int o = 1; o <= 2; o <<= 1) {
                unsigned long long other =
                    __shfl_xor_sync(0xFFFFFFFFu, best, o);
                best = (other < best) ? other : best;
            }
            if ((lane & 3) == 0)
                atomicMin(&best_s[wm + ma * 16 + h * 8 + erow], best);
        }
    }
    __syncthreads();
    if (tid < BM)
        atomicMin(&g_best[rowBase + tid], best_s[tid]);
}

// ---------------------------------------------------------------------------
__global__ void write_inds_kernel(float* __restrict__ out, int n_rows) {
    int r = blockIdx.x * blockDim.x + threadIdx.x;
    if (r < n_rows)
        out[r] = (float)(unsigned int)(g_best[r] & 0xFFFFFFFFull);
}

__global__ void gather_kernel(const float* __restrict__ cb,
                              float* __restrict__ out,
                              int n_rows, long long offset) {
    int r = blockIdx.x * blockDim.x + threadIdx.x;
    int d = blockIdx.y;
    if (r >= n_rows) return;
    unsigned int ind = (unsigned int)(g_best[r] & 0xFFFFFFFFull);
    out[offset + (size_t)d * n_rows + r] = cb[(size_t)d * NC + ind];
}

// ---------------------------------------------------------------------------
extern "C" void kernel_launch(void* const* d_in, const int* in_sizes, int n_in,
                              void* d_out, int out_size) {
    const float* x  = (const float*)d_in[0];
    const float* cb = (const float*)d_in[1];
    float* out = (float*)d_out;

    int n_rows = in_sizes[0] / DIM;
    if (n_rows > MAX_ROWS) n_rows = MAX_ROWS;

    static int smem_set = 0;
    if (!smem_set) {
        cudaFuncSetAttribute(gemm_mma_kernel,
                             cudaFuncAttributeMaxDynamicSharedMemorySize, SMEM_DYN);
        smem_set = 1;
    }

    // phase 0: prep
    normalize_split_kernel<<<(n_rows * 32 + 255) / 256, 256>>>(x, n_rows);
    dim3 tg(NC / 32, DIM / 32);
    transpose_split_kernel<<<tg, dim3(32, 8)>>>(cb);
    d2_kernel<<<(NC + 255) / 256, 256>>>(cb);
    init_best_kernel<<<(n_rows + 255) / 256, 256>>>(n_rows);

    // phase 1: tensor-core (mma.sync) GEMM + fused argmin
    int mtiles = (n_rows + BM - 1) / BM;
    gemm_mma_kernel<<<mtiles * TILES_N, 256, SMEM_DYN>>>(mtiles);

    // phase 2: outputs [inds (n_rows)] ++ [quantized (DIM*n_rows)]
    long long full = (long long)n_rows + (long long)n_rows * DIM;
    if ((long long)out_size >= full) {
        write_inds_kernel<<<(n_rows + 255) / 256, 256>>>(out, n_rows);
        dim3 g2((n_rows + 255) / 256, DIM);
        gather_kernel<<<g2, 256>>>(cb, out, n_rows, (long long)n_rows);
    } else if ((long long)out_size == (long long)n_rows * DIM) {
        dim3 g2((n_rows + 255) / 256, DIM);
        gather_kernel<<<g2, 256>>>(cb, out, n_rows, 0);
    } else {
        write_inds_kernel<<<(n_rows + 255) / 256, 256>>>(out, n_rows);
    }
}

// round 11
// speedup vs baseline: 8.1935x; 1.8892x over previous
#include <cuda_runtime.h>
#include <cuda_bf16.h>
#include <stdint.h>

#define DIM 1280
#define NC  8192
#define MAX_ROWS 16384

#define BM 128
#define BN 256
#define BK 64                      // bf16 k-elements per chunk (128 B rows)
#define NCH (DIM / BK)             // 20
#define TILES_N (NC / BN)          // 32
#define NSTAGE 3

// rigorous margin: |approx-exact| <= 2 * 2^-7 * max_row sum|a_k b_k| ~ 1.0e-2 worst case
#define EPS 1.3e-2f

// stage layout: A 128x64 bf16 = 16 KB, B 256x64 bf16 = 32 KB
#define ST_A 0
#define ST_B 16384
#define STAGE_BYTES 49152
#define SMEM_DYN (NSTAGE * STAGE_BYTES)   // 147456

#define MAXCAND 256

// ---- device scratch ----
__device__ float         g_xf[(size_t)MAX_ROWS * DIM];   // normalized x fp32
__device__ __nv_bfloat16 g_a_hi[(size_t)MAX_ROWS * DIM];
__device__ float         g_bT[(size_t)NC * DIM];         // codebook^T fp32
__device__ __nv_bfloat16 g_b_hi[(size_t)NC * DIM];
__device__ float         g_d2[NC];
__device__ float         g_dist[(size_t)MAX_ROWS * NC];  // approx distances
__device__ int           g_idx[MAX_ROWS];

// ---------------------------------------------------------------------------
__device__ __forceinline__ uint32_t smem_u32(const void* p) {
    uint32_t a;
    asm("{ .reg .u64 t; cvta.to.shared.u64 t, %1; cvt.u32.u64 %0, t; }"
        : "=r"(a) : "l"(p));
    return a;
}
__device__ __forceinline__ unsigned int fkey(float f) {
    unsigned int u = __float_as_uint(f);
    return (u & 0x80000000u) ? ~u : (u | 0x80000000u);
}
#define SWZ(o) ((o) ^ ((((uint32_t)(o)) >> 3) & 0x70))

__device__ __forceinline__ void cp16(uint32_t dst, const void* src) {
    asm volatile("cp.async.cg.shared.global [%0], [%1], 16;" :: "r"(dst), "l"(src));
}
#define CP_COMMIT() asm volatile("cp.async.commit_group;" ::: "memory")

__device__ __forceinline__ void ldsm4(uint32_t& r0, uint32_t& r1, uint32_t& r2,
                                      uint32_t& r3, uint32_t addr) {
    asm volatile("ldmatrix.sync.aligned.m8n8.x4.shared.b16 {%0,%1,%2,%3}, [%4];"
                 : "=r"(r0), "=r"(r1), "=r"(r2), "=r"(r3) : "r"(addr));
}
__device__ __forceinline__ void mma_bf16(float* c, uint32_t a0, uint32_t a1,
                                         uint32_t a2, uint32_t a3,
                                         uint32_t b0, uint32_t b1) {
    asm volatile(
        "mma.sync.aligned.m16n8k16.row.col.f32.bf16.bf16.f32 "
        "{%0,%1,%2,%3}, {%4,%5,%6,%7}, {%8,%9}, {%0,%1,%2,%3};"
        : "+f"(c[0]), "+f"(c[1]), "+f"(c[2]), "+f"(c[3])
        : "r"(a0), "r"(a1), "r"(a2), "r"(a3), "r"(b0), "r"(b1));
}

// ---------------------------------------------------------------------------
__global__ void normalize_split_kernel(const float* __restrict__ x, int n_rows) {
    int gwarp = (blockIdx.x * blockDim.x + threadIdx.x) >> 5;
    int lane  = threadIdx.x & 31;
    if (gwarp >= n_rows) return;
    const float* xr = x + (size_t)gwarp * DIM;
    float s = 0.f;
    #pragma unroll 4
    for (int k = lane; k < DIM; k += 32) { float v = xr[k]; s = fmaf(v, v, s); }
    #pragma unroll
    for (int o = 16; o; o >>= 1) s += __shfl_xor_sync(0xFFFFFFFFu, s, o);
    float norm = fmaxf(sqrtf(s), 1e-12f);
    float* xo = g_xf + (size_t)gwarp * DIM;
    __nv_bfloat16* oh = g_a_hi + (size_t)gwarp * DIM;
    #pragma unroll 4
    for (int k = lane; k < DIM; k += 32) {
        float v = xr[k] / norm;
        xo[k] = v;
        oh[k] = __float2bfloat16(v);
    }
}

__global__ void transpose_split_kernel(const float* __restrict__ cb) {
    __shared__ float t[32][33];
    int n0 = blockIdx.x * 32;
    int k0 = blockIdx.y * 32;
    int tx = threadIdx.x, ty = threadIdx.y;  // 32 x 8
    #pragma unroll
    for (int j = 0; j < 4; j++)
        t[ty + 8 * j][tx] = cb[(size_t)(k0 + ty + 8 * j) * NC + n0 + tx];
    __syncthreads();
    #pragma unroll
    for (int j = 0; j < 4; j++) {
        int n = n0 + ty + 8 * j;
        int k = k0 + tx;
        float v = t[tx][ty + 8 * j];
        g_bT[(size_t)n * DIM + k] = v;
        g_b_hi[(size_t)n * DIM + k] = __float2bfloat16(v);
    }
}

__global__ void d2_kernel(const float* __restrict__ cb) {
    int c = blockIdx.x * blockDim.x + threadIdx.x;
    if (c >= NC) return;
    float s = 0.f;
    #pragma unroll 4
    for (int k = 0; k < DIM; k++) { float v = cb[(size_t)k * NC + c]; s = fmaf(v, v, s); }
    g_d2[c] = s;
}

// ---------------------------------------------------------------------------
// single-pass bf16 mma.sync GEMM 128x256, warp tile 64x64, 3-stage pipeline.
// epilogue stores approx dist = d2 - 2*d3 (streaming).
__global__ __launch_bounds__(256, 1)
void gemm_mma_kernel(int mtiles) {
    extern __shared__ char smem[];
    __shared__ float d2s[BN];

    const uint32_t sb = smem_u32(smem);
    const int tid  = threadIdx.x;
    const int wid  = tid >> 5;
    const int lane = tid & 31;

    int bid = blockIdx.x;
    int mt = bid % mtiles;
    int nt = bid / mtiles;
    const int rowBase = mt * BM;
    const int colBase = nt * BN;

    d2s[tid] = g_d2[colBase + tid];        // 256 threads cover all BN=256 entries
    __syncthreads();

    const __nv_bfloat16* Ah = g_a_hi + (size_t)rowBase * DIM;
    const __nv_bfloat16* Bh = g_b_hi + (size_t)colBase * DIM;

    auto load_chunk = [&](int c, int st) {
        uint32_t base = sb + st * STAGE_BYTES;
        int kb = c * BK;
        #pragma unroll
        for (int j = 0; j < 4; j++) {              // A: 128 rows
            int i = tid + j * 256;
            int row = i >> 3, c16 = i & 7;
            uint32_t off = SWZ(row * 128 + c16 * 16);
            cp16(base + ST_A + off, Ah + (size_t)row * DIM + kb + c16 * 8);
        }
        #pragma unroll
        for (int j = 0; j < 8; j++) {              // B: 256 rows
            int i = tid + j * 256;
            int row = i >> 3, c16 = i & 7;
            uint32_t off = SWZ(row * 128 + c16 * 16);
            cp16(base + ST_B + off, Bh + (size_t)row * DIM + kb + c16 * 8);
        }
        CP_COMMIT();
    };

    // warp tiling: 2 (M) x 4 (N), warp tile 64 x 64
    const int wm = (wid >> 2) * 64;
    const int wn = (wid & 3) * 64;

    float acc[4][8][4];
    #pragma unroll
    for (int i = 0; i < 4; i++)
        #pragma unroll
        for (int j = 0; j < 8; j++)
            #pragma unroll
            for (int k = 0; k < 4; k++) acc[i][j][k] = 0.f;

    const int lm = lane >> 3;
    const int lr = lane & 7;
    const int a_row  = wm + ((lm & 1) << 3) + lr;
    const int a_koff = (lm >> 1) << 4;
    const int b_row  = wn + ((lm >> 1) << 3) + lr;
    const int b_koff = (lm & 1) << 4;

    load_chunk(0, 0);
    load_chunk(1, 1);

    for (int c = 0; c < NCH; c++) {
        if (c + 1 < NCH) {
            asm volatile("cp.async.wait_group 1;" ::: "memory");
        } else {
            asm volatile("cp.async.wait_group 0;" ::: "memory");
        }
        __syncthreads();
        if (c + 2 < NCH) load_chunk(c + 2, (c + 2) % NSTAGE);

        uint32_t base = sb + (c % NSTAGE) * STAGE_BYTES;
        #pragma unroll
        for (int ks = 0; ks < 4; ks++) {
            uint32_t ah[4][4], bh[8][2];
            #pragma unroll
            for (int ma = 0; ma < 4; ma++) {
                uint32_t ra = SWZ((a_row + ma * 16) * 128 + ks * 32 + a_koff);
                ldsm4(ah[ma][0], ah[ma][1], ah[ma][2], ah[ma][3], base + ST_A + ra);
            }
            #pragma unroll
            for (int nb = 0; nb < 4; nb++) {
                uint32_t rb = SWZ((b_row + nb * 16) * 128 + ks * 32 + b_koff);
                ldsm4(bh[2 * nb][0], bh[2 * nb][1], bh[2 * nb + 1][0], bh[2 * nb + 1][1],
                      base + ST_B + rb);
            }
            #pragma unroll
            for (int ma = 0; ma < 4; ma++)
                #pragma unroll
                for (int na = 0; na < 8; na++)
                    mma_bf16(acc[ma][na], ah[ma][0], ah[ma][1], ah[ma][2], ah[ma][3],
                             bh[na][0], bh[na][1]);
        }
    }

    // ---- epilogue: store approx distances (streaming) ----
    const int erow = lane >> 2;
    const int ecol = 2 * (lane & 3);
    #pragma unroll
    for (int ma = 0; ma < 4; ma++) {
        #pragma unroll
        for (int h = 0; h < 2; h++) {
            int row = rowBase + wm + ma * 16 + h * 8 + erow;
            #pragma unroll
            for (int na = 0; na < 8; na++) {
                int cl = wn + na * 8 + ecol;
                float2 d;
                d.x = d2s[cl]     - 2.0f * acc[ma][na][2 * h];
                d.y = d2s[cl + 1] - 2.0f * acc[ma][na][2 * h + 1];
                __stcs((float2*)(g_dist + (size_t)row * NC + colBase + cl), d);
            }
        }
    }
}

// ---------------------------------------------------------------------------
// per-row: approx min, candidates within EPS, exact fp32 refine (warp/candidate)
__global__ __launch_bounds__(256, 4)
void select_kernel() {
    __shared__ unsigned long long wmin[8];
    __shared__ unsigned long long rowmin_s;
    __shared__ unsigned long long sbest;
    __shared__ int cands[MAXCAND];
    __shared__ int ncand;

    const int row  = blockIdx.x;
    const int tid  = threadIdx.x;
    const int wid  = tid >> 5;
    const int lane = tid & 31;

    const float* dr = g_dist + (size_t)row * NC;

    float v[32];
    unsigned long long key = ~0ull;
    #pragma unroll
    for (int j = 0; j < 32; j++) {
        int c = tid + 256 * j;
        v[j] = dr[c];
        unsigned long long pk = ((unsigned long long)fkey(v[j]) << 32) | (unsigned int)c;
        key = (pk < key) ? pk : key;
    }
    #pragma unroll
    for (int o = 16; o; o >>= 1) {
        unsigned long long other = __shfl_xor_sync(0xFFFFFFFFu, key, o);
        key = (other < key) ? other : key;
    }
    if (lane == 0) wmin[wid] = key;
    if (tid == 0) { ncand = 0; sbest = ~0ull; }
    __syncthreads();
    if (tid == 0) {
        unsigned long long k = wmin[0];
        #pragma unroll
        for (int w = 1; w < 8; w++) k = (wmin[w] < k) ? wmin[w] : k;
        rowmin_s = k;
    }
    __syncthreads();

    unsigned long long rk = rowmin_s;
    unsigned int mku = (unsigned int)(rk >> 32);
    float m = (mku & 0x80000000u) ? __uint_as_float(mku & 0x7FFFFFFFu)
                                  : __uint_as_float(~mku);
    float thr = m + EPS;

    #pragma unroll
    for (int j = 0; j < 32; j++) {
        if (v[j] <= thr) {
            int p = atomicAdd(&ncand, 1);
            if (p < MAXCAND) cands[p] = tid + 256 * j;
        }
    }
    __syncthreads();

    int nc = ncand; if (nc > MAXCAND) nc = MAXCAND;
    if (nc <= 1) {
        if (tid == 0) g_idx[row] = (int)(rk & 0xFFFFFFFFull);
        return;
    }

    // exact fp32 refine: one warp per candidate, round-robin
    const float* xr = g_xf + (size_t)row * DIM;
    for (int ci = wid; ci < nc; ci += 8) {
        int c = cands[ci];
        const float* bc = g_bT + (size_t)c * DIM;
        float p = 0.f;
        #pragma unroll
        for (int e = 0; e < DIM / 32; e++) {
            int k = lane + 32 * e;
            p = fmaf(xr[k], bc[k], p);
        }
        #pragma unroll
        for (int o = 16; o; o >>= 1) p += __shfl_xor_sync(0xFFFFFFFFu, p, o);
        if (lane == 0) {
            float dist = g_d2[c] - 2.0f * p;
            unsigned long long pk =
                ((unsigned long long)fkey(dist) << 32) | (unsigned int)c;
            atomicMin(&sbest, pk);
        }
    }
    __syncthreads();
    if (tid == 0) g_idx[row] = (int)(sbest & 0xFFFFFFFFull);
}

// ---------------------------------------------------------------------------
__global__ void write_inds_kernel(float* __restrict__ out, int n_rows) {
    int r = blockIdx.x * blockDim.x + threadIdx.x;
    if (r < n_rows) out[r] = (float)g_idx[r];
}

__global__ void gather_kernel(const float* __restrict__ cb,
                              float* __restrict__ out,
                              int n_rows, long long offset) {
    int r = blockIdx.x * blockDim.x + threadIdx.x;
    int d = blockIdx.y;
    if (r >= n_rows) return;
    int ind = g_idx[r];
    out[offset + (size_t)d * n_rows + r] = cb[(size_t)d * NC + ind];
}

// ---------------------------------------------------------------------------
extern "C" void kernel_launch(void* const* d_in, const int* in_sizes, int n_in,
                              void* d_out, int out_size) {
    const float* x  = (const float*)d_in[0];
    const float* cb = (const float*)d_in[1];
    float* out = (float*)d_out;

    int n_rows = in_sizes[0] / DIM;
    if (n_rows > MAX_ROWS) n_rows = MAX_ROWS;

    static int smem_set = 0;
    if (!smem_set) {
        cudaFuncSetAttribute(gemm_mma_kernel,
                             cudaFuncAttributeMaxDynamicSharedMemorySize, SMEM_DYN);
        smem_set = 1;
    }

    // phase 0: prep
    normalize_split_kernel<<<(n_rows * 32 + 255) / 256, 256>>>(x, n_rows);
    dim3 tg(NC / 32, DIM / 32);
    transpose_split_kernel<<<tg, dim3(32, 8)>>>(cb);
    d2_kernel<<<(NC + 255) / 256, 256>>>(cb);

    // phase 1: single-pass bf16 GEMM -> approx dist matrix
    int mtiles = (n_rows + BM - 1) / BM;
    gemm_mma_kernel<<<mtiles * TILES_N, 256, SMEM_DYN>>>(mtiles);

    // phase 2: per-row candidate selection + exact rescue
    select_kernel<<<n_rows, 256>>>();

    // phase 3: outputs [inds (n_rows)] ++ [quantized (DIM*n_rows)]
    long long full = (long long)n_rows + (long long)n_rows * DIM;
    if ((long long)out_size >= full) {
        write_inds_kernel<<<(n_rows + 255) / 256, 256>>>(out, n_rows);
        dim3 g2((n_rows + 255) / 256, DIM);
        gather_kernel<<<g2, 256>>>(cb, out, n_rows, (long long)n_rows);
    } else if ((long long)out_size == (long long)n_rows * DIM) {
        dim3 g2((n_rows + 255) / 256, DIM);
        gather_kernel<<<g2, 256>>>(cb, out, n_rows, 0);
    } else {
        write_inds_kernel<<<(n_rows + 255) / 256, 256>>>(out, n_rows);
    }
}

// round 12
// speedup vs baseline: 8.7732x; 1.0707x over previous
#include <cuda_runtime.h>
#include <cuda_fp16.h>
#include <stdint.h>

#define DIM 1280
#define NC  8192
#define MAX_ROWS 16384

#define BM 128
#define BN 256
#define BK 64                      // fp16 k-elements per chunk (128 B rows)
#define NCH (DIM / BK)             // 20
#define TILES_N (NC / BN)          // 32
#define NSTAGE 3

// rigorous margin: approx err (2-sided) <= 2*2^-11*||a||*||b|| ~ 8.8e-4,
// + fp16 dist storage rounding (2-sided) ~ 6e-4  => 1.5e-3 < EPS
#define EPS 2e-3f

// stage layout: A 128x64 fp16 = 16 KB, B 256x64 fp16 = 32 KB
#define ST_A 0
#define ST_B 16384
#define STAGE_BYTES 49152
#define SMEM_DYN (NSTAGE * STAGE_BYTES)   // 147456

#define MAXCAND 256

// ---- device scratch ----
__device__ float  g_xf[(size_t)MAX_ROWS * DIM];   // normalized x fp32
__device__ __half g_a_h[(size_t)MAX_ROWS * DIM];
__device__ float  g_bT[(size_t)NC * DIM];         // codebook^T fp32
__device__ __half g_b_h[(size_t)NC * DIM];
__device__ float  g_d2[NC];
__device__ __half g_dist[(size_t)MAX_ROWS * NC];  // approx distances (fp16)
__device__ int    g_idx[MAX_ROWS];

// ---------------------------------------------------------------------------
__device__ __forceinline__ uint32_t smem_u32(const void* p) {
    uint32_t a;
    asm("{ .reg .u64 t; cvta.to.shared.u64 t, %1; cvt.u32.u64 %0, t; }"
        : "=r"(a) : "l"(p));
    return a;
}
__device__ __forceinline__ unsigned int fkey(float f) {
    unsigned int u = __float_as_uint(f);
    return (u & 0x80000000u) ? ~u : (u | 0x80000000u);
}
#define SWZ(o) ((o) ^ ((((uint32_t)(o)) >> 3) & 0x70))

__device__ __forceinline__ void cp16(uint32_t dst, const void* src) {
    asm volatile("cp.async.cg.shared.global [%0], [%1], 16;" :: "r"(dst), "l"(src));
}
#define CP_COMMIT() asm volatile("cp.async.commit_group;" ::: "memory")

__device__ __forceinline__ void ldsm4(uint32_t& r0, uint32_t& r1, uint32_t& r2,
                                      uint32_t& r3, uint32_t addr) {
    asm volatile("ldmatrix.sync.aligned.m8n8.x4.shared.b16 {%0,%1,%2,%3}, [%4];"
                 : "=r"(r0), "=r"(r1), "=r"(r2), "=r"(r3) : "r"(addr));
}
__device__ __forceinline__ void mma_f16(float* c, uint32_t a0, uint32_t a1,
                                        uint32_t a2, uint32_t a3,
                                        uint32_t b0, uint32_t b1) {
    asm volatile(
        "mma.sync.aligned.m16n8k16.row.col.f32.f16.f16.f32 "
        "{%0,%1,%2,%3}, {%4,%5,%6,%7}, {%8,%9}, {%0,%1,%2,%3};"
        : "+f"(c[0]), "+f"(c[1]), "+f"(c[2]), "+f"(c[3])
        : "r"(a0), "r"(a1), "r"(a2), "r"(a3), "r"(b0), "r"(b1));
}

// ---------------------------------------------------------------------------
__global__ void normalize_split_kernel(const float* __restrict__ x, int n_rows) {
    int gwarp = (blockIdx.x * blockDim.x + threadIdx.x) >> 5;
    int lane  = threadIdx.x & 31;
    if (gwarp >= n_rows) return;
    const float* xr = x + (size_t)gwarp * DIM;
    float s = 0.f;
    #pragma unroll 4
    for (int k = lane; k < DIM; k += 32) { float v = xr[k]; s = fmaf(v, v, s); }
    #pragma unroll
    for (int o = 16; o; o >>= 1) s += __shfl_xor_sync(0xFFFFFFFFu, s, o);
    float norm = fmaxf(sqrtf(s), 1e-12f);
    float* xo = g_xf + (size_t)gwarp * DIM;
    __half* oh = g_a_h + (size_t)gwarp * DIM;
    #pragma unroll 4
    for (int k = lane; k < DIM; k += 32) {
        float v = xr[k] / norm;
        xo[k] = v;
        oh[k] = __float2half_rn(v);
    }
}

__global__ void transpose_split_kernel(const float* __restrict__ cb) {
    __shared__ float t[32][33];
    int n0 = blockIdx.x * 32;
    int k0 = blockIdx.y * 32;
    int tx = threadIdx.x, ty = threadIdx.y;  // 32 x 8
    #pragma unroll
    for (int j = 0; j < 4; j++)
        t[ty + 8 * j][tx] = cb[(size_t)(k0 + ty + 8 * j) * NC + n0 + tx];
    __syncthreads();
    #pragma unroll
    for (int j = 0; j < 4; j++) {
        int n = n0 + ty + 8 * j;
        int k = k0 + tx;
        float v = t[tx][ty + 8 * j];
        g_bT[(size_t)n * DIM + k] = v;
        g_b_h[(size_t)n * DIM + k] = __float2half_rn(v);
    }
}

__global__ void d2_kernel(const float* __restrict__ cb) {
    int c = blockIdx.x * blockDim.x + threadIdx.x;
    if (c >= NC) return;
    float s = 0.f;
    #pragma unroll 4
    for (int k = 0; k < DIM; k++) { float v = cb[(size_t)k * NC + c]; s = fmaf(v, v, s); }
    g_d2[c] = s;
}

// ---------------------------------------------------------------------------
// single-pass fp16 mma.sync GEMM 128x256, warp tile 64x64, 3-stage pipeline.
// epilogue stores approx dist = d2 - 2*d3 as fp16 (streaming).
__global__ __launch_bounds__(256, 1)
void gemm_mma_kernel(int mtiles) {
    extern __shared__ char smem[];
    __shared__ float d2s[BN];

    const uint32_t sb = smem_u32(smem);
    const int tid  = threadIdx.x;
    const int wid  = tid >> 5;
    const int lane = tid & 31;

    int bid = blockIdx.x;
    int mt = bid % mtiles;
    int nt = bid / mtiles;
    const int rowBase = mt * BM;
    const int colBase = nt * BN;

    d2s[tid] = g_d2[colBase + tid];        // 256 threads cover BN=256
    __syncthreads();

    const __half* Ah = g_a_h + (size_t)rowBase * DIM;
    const __half* Bh = g_b_h + (size_t)colBase * DIM;

    auto load_chunk = [&](int c, int st) {
        uint32_t base = sb + st * STAGE_BYTES;
        int kb = c * BK;
        #pragma unroll
        for (int j = 0; j < 4; j++) {              // A: 128 rows
            int i = tid + j * 256;
            int row = i >> 3, c16 = i & 7;
            uint32_t off = SWZ(row * 128 + c16 * 16);
            cp16(base + ST_A + off, Ah + (size_t)row * DIM + kb + c16 * 8);
        }
        #pragma unroll
        for (int j = 0; j < 8; j++) {              // B: 256 rows
            int i = tid + j * 256;
            int row = i >> 3, c16 = i & 7;
            uint32_t off = SWZ(row * 128 + c16 * 16);
            cp16(base + ST_B + off, Bh + (size_t)row * DIM + kb + c16 * 8);
        }
        CP_COMMIT();
    };

    // warp tiling: 2 (M) x 4 (N), warp tile 64 x 64
    const int wm = (wid >> 2) * 64;
    const int wn = (wid & 3) * 64;

    float acc[4][8][4];
    #pragma unroll
    for (int i = 0; i < 4; i++)
        #pragma unroll
        for (int j = 0; j < 8; j++)
            #pragma unroll
            for (int k = 0; k < 4; k++) acc[i][j][k] = 0.f;

    const int lm = lane >> 3;
    const int lr = lane & 7;
    const int a_row  = wm + ((lm & 1) << 3) + lr;
    const int a_koff = (lm >> 1) << 4;
    const int b_row  = wn + ((lm >> 1) << 3) + lr;
    const int b_koff = (lm & 1) << 4;

    load_chunk(0, 0);
    load_chunk(1, 1);

    for (int c = 0; c < NCH; c++) {
        if (c + 1 < NCH) {
            asm volatile("cp.async.wait_group 1;" ::: "memory");
        } else {
            asm volatile("cp.async.wait_group 0;" ::: "memory");
        }
        __syncthreads();
        if (c + 2 < NCH) load_chunk(c + 2, (c + 2) % NSTAGE);

        uint32_t base = sb + (c % NSTAGE) * STAGE_BYTES;
        #pragma unroll
        for (int ks = 0; ks < 4; ks++) {
            uint32_t ah[4][4], bh[8][2];
            #pragma unroll
            for (int ma = 0; ma < 4; ma++) {
                uint32_t ra = SWZ((a_row + ma * 16) * 128 + ks * 32 + a_koff);
                ldsm4(ah[ma][0], ah[ma][1], ah[ma][2], ah[ma][3], base + ST_A + ra);
            }
            #pragma unroll
            for (int nb = 0; nb < 4; nb++) {
                uint32_t rb = SWZ((b_row + nb * 16) * 128 + ks * 32 + b_koff);
                ldsm4(bh[2 * nb][0], bh[2 * nb][1], bh[2 * nb + 1][0], bh[2 * nb + 1][1],
                      base + ST_B + rb);
            }
            #pragma unroll
            for (int ma = 0; ma < 4; ma++)
                #pragma unroll
                for (int na = 0; na < 8; na++)
                    mma_f16(acc[ma][na], ah[ma][0], ah[ma][1], ah[ma][2], ah[ma][3],
                            bh[na][0], bh[na][1]);
        }
    }

    // ---- epilogue: store approx distances as fp16 (streaming) ----
    const int erow = lane >> 2;
    const int ecol = 2 * (lane & 3);
    #pragma unroll
    for (int ma = 0; ma < 4; ma++) {
        #pragma unroll
        for (int h = 0; h < 2; h++) {
            int row = rowBase + wm + ma * 16 + h * 8 + erow;
            #pragma unroll
            for (int na = 0; na < 8; na++) {
                int cl = wn + na * 8 + ecol;
                float dx = d2s[cl]     - 2.0f * acc[ma][na][2 * h];
                float dy = d2s[cl + 1] - 2.0f * acc[ma][na][2 * h + 1];
                __half2 hv = __floats2half2_rn(dx, dy);
                __stcs((uint32_t*)(g_dist + (size_t)row * NC + colBase + cl),
                       *(uint32_t*)&hv);
            }
        }
    }
}

// ---------------------------------------------------------------------------
// per-row: approx min, candidates within EPS, exact fp32 refine (warp/candidate)
__global__ __launch_bounds__(256, 4)
void select_kernel() {
    __shared__ unsigned long long wmin[8];
    __shared__ unsigned long long rowmin_s;
    __shared__ unsigned long long sbest;
    __shared__ int cands[MAXCAND];
    __shared__ int ncand;

    const int row  = blockIdx.x;
    const int tid  = threadIdx.x;
    const int wid  = tid >> 5;
    const int lane = tid & 31;

    const uint4* dr4 = (const uint4*)(g_dist + (size_t)row * NC);

    float v[32];
    unsigned long long key = ~0ull;
    #pragma unroll
    for (int j = 0; j < 4; j++) {
        uint4 q = dr4[tid + 256 * j];
        int cbase = (tid + 256 * j) * 8;
        uint32_t w[4] = {q.x, q.y, q.z, q.w};
        #pragma unroll
        for (int p = 0; p < 4; p++) {
            __half2 h2 = *(__half2*)&w[p];
            float2 f = __half22float2(h2);
            v[j * 8 + 2 * p]     = f.x;
            v[j * 8 + 2 * p + 1] = f.y;
            unsigned long long pk0 =
                ((unsigned long long)fkey(f.x) << 32) | (unsigned int)(cbase + 2 * p);
            unsigned long long pk1 =
                ((unsigned long long)fkey(f.y) << 32) | (unsigned int)(cbase + 2 * p + 1);
            key = (pk0 < key) ? pk0 : key;
            key = (pk1 < key) ? pk1 : key;
        }
    }
    #pragma unroll
    for (int o = 16; o; o >>= 1) {
        unsigned long long other = __shfl_xor_sync(0xFFFFFFFFu, key, o);
        key = (other < key) ? other : key;
    }
    if (lane == 0) wmin[wid] = key;
    if (tid == 0) { ncand = 0; sbest = ~0ull; }
    __syncthreads();
    if (tid == 0) {
        unsigned long long k = wmin[0];
        #pragma unroll
        for (int w = 1; w < 8; w++) k = (wmin[w] < k) ? wmin[w] : k;
        rowmin_s = k;
    }
    __syncthreads();

    unsigned long long rk = rowmin_s;
    unsigned int mku = (unsigned int)(rk >> 32);
    float m = (mku & 0x80000000u) ? __uint_as_float(mku & 0x7FFFFFFFu)
                                  : __uint_as_float(~mku);
    float thr = m + EPS;

    #pragma unroll
    for (int j = 0; j < 32; j++) {
        if (v[j] <= thr) {
            int c = ((tid + 256 * (j >> 3)) * 8) + (j & 7);
            int p = atomicAdd(&ncand, 1);
            if (p < MAXCAND) cands[p] = c;
        }
    }
    __syncthreads();

    int nc = ncand; if (nc > MAXCAND) nc = MAXCAND;
    if (nc <= 1) {
        if (tid == 0) g_idx[row] = (int)(rk & 0xFFFFFFFFull);
        return;
    }

    // exact fp32 refine: one warp per candidate, round-robin
    const float* xr = g_xf + (size_t)row * DIM;
    for (int ci = wid; ci < nc; ci += 8) {
        int c = cands[ci];
        const float* bc = g_bT + (size_t)c * DIM;
        float p = 0.f;
        #pragma unroll
        for (int e = 0; e < DIM / 32; e++) {
            int k = lane + 32 * e;
            p = fmaf(xr[k], bc[k], p);
        }
        #pragma unroll
        for (int o = 16; o; o >>= 1) p += __shfl_xor_sync(0xFFFFFFFFu, p, o);
        if (lane == 0) {
            float dist = g_d2[c] - 2.0f * p;
            unsigned long long pk =
                ((unsigned long long)fkey(dist) << 32) | (unsigned int)c;
            atomicMin(&sbest, pk);
        }
    }
    __syncthreads();
    if (tid == 0) g_idx[row] = (int)(sbest & 0xFFFFFFFFull);
}

// ---------------------------------------------------------------------------
__global__ void write_inds_kernel(float* __restrict__ out, int n_rows) {
    int r = blockIdx.x * blockDim.x + threadIdx.x;
    if (r < n_rows) out[r] = (float)g_idx[r];
}

__global__ void gather_kernel(const float* __restrict__ cb,
                              float* __restrict__ out,
                              int n_rows, long long offset) {
    int r = blockIdx.x * blockDim.x + threadIdx.x;
    int d = blockIdx.y;
    if (r >= n_rows) return;
    int ind = g_idx[r];
    out[offset + (size_t)d * n_rows + r] = cb[(size_t)d * NC + ind];
}

// ---------------------------------------------------------------------------
extern "C" void kernel_launch(void* const* d_in, const int* in_sizes, int n_in,
                              void* d_out, int out_size) {
    const float* x  = (const float*)d_in[0];
    const float* cb = (const float*)d_in[1];
    float* out = (float*)d_out;

    int n_rows = in_sizes[0] / DIM;
    if (n_rows > MAX_ROWS) n_rows = MAX_ROWS;

    static int smem_set = 0;
    if (!smem_set) {
        cudaFuncSetAttribute(gemm_mma_kernel,
                             cudaFuncAttributeMaxDynamicSharedMemorySize, SMEM_DYN);
        smem_set = 1;
    }

    // phase 0: prep
    normalize_split_kernel<<<(n_rows * 32 + 255) / 256, 256>>>(x, n_rows);
    dim3 tg(NC / 32, DIM / 32);
    transpose_split_kernel<<<tg, dim3(32, 8)>>>(cb);
    d2_kernel<<<(NC + 255) / 256, 256>>>(cb);

    // phase 1: single-pass fp16 GEMM -> approx dist matrix (fp16)
    int mtiles = (n_rows + BM - 1) / BM;
    gemm_mma_kernel<<<mtiles * TILES_N, 256, SMEM_DYN>>>(mtiles);

    // phase 2: per-row candidate selection + exact rescue
    select_kernel<<<n_rows, 256>>>();

    // phase 3: outputs [inds (n_rows)] ++ [quantized (DIM*n_rows)]
    long long full = (long long)n_rows + (long long)n_rows * DIM;
    if ((long long)out_size >= full) {
        write_inds_kernel<<<(n_rows + 255) / 256, 256>>>(out, n_rows);
        dim3 g2((n_rows + 255) / 256, DIM);
        gather_kernel<<<g2, 256>>>(cb, out, n_rows, (long long)n_rows);
    } else if ((long long)out_size == (long long)n_rows * DIM) {
        dim3 g2((n_rows + 255) / 256, DIM);
        gather_kernel<<<g2, 256>>>(cb, out, n_rows, 0);
    } else {
        write_inds_kernel<<<(n_rows + 255) / 256, 256>>>(out, n_rows);
    }
}